// round 13
// baseline (speedup 1.0000x reference)
#include <cuda_runtime.h>
#include <cuda_bf16.h>
#include <math.h>
#include <stdint.h>

// Problem constants (fixed by the dataset)
#define Nn   50000
#define Ee   640000
#define Pp   1024
#define ENt  (Ee + Nn)          // edges + self loops
#define NBS  49                 // ceil(N/1024) scan blocks
#define NT   391                // ceil(N/128) M tiles
#define SMSTG 40960             // bytes per k_mma pipeline stage

// ---------------- device scratch (no allocations allowed) ----------------
__device__ __align__(16) float d_h [Nn * 128];
__device__ __align__(16) float d_xl[Nn * 128];
__device__ __align__(16) float d_xr[Nn * 128];
__device__ __align__(16) float d_loop_attr[Nn * 4];
__device__ int   d_deg[Nn];
__device__ int   d_inc[Nn];
__device__ int   d_bsum[64];
__device__ int   d_rowptr[Nn + 1];
__device__ int   d_cursor[Nn];
__device__ __align__(16) int2 d_cse[ENt];          // (src, eid) packed
__device__ float d_gb[4 * 256];                    // per-layer gamma(128)/beta(128)
__device__ int   d_tag[Nn];
// bf16 hi/lo row-major MMA operand images
__device__ __align__(16) unsigned char d_hA[(size_t)NT * 65536];
__device__ __align__(16) unsigned char d_Bw[8 * 65536];

// ---------------- generic helpers ----------------
__device__ __forceinline__ float geluf(float v) {
    return 0.5f * v * (1.0f + erff(v * 0.70710678118654752440f));
}
__device__ __forceinline__ float wsum(float v) {
    #pragma unroll
    for (int o = 16; o > 0; o >>= 1) v += __shfl_xor_sync(0xffffffffu, v, o);
    return v;
}
__device__ __forceinline__ unsigned int pack_hi(float a, float b) {
    return (unsigned int)__bfloat16_as_ushort(__float2bfloat16(a)) |
           ((unsigned int)__bfloat16_as_ushort(__float2bfloat16(b)) << 16);
}
__device__ __forceinline__ unsigned int pack_lo(float a, float b) {
    __nv_bfloat16 ha = __float2bfloat16(a), hb = __float2bfloat16(b);
    return (unsigned int)__bfloat16_as_ushort(__float2bfloat16(a - __bfloat162float(ha))) |
           ((unsigned int)__bfloat16_as_ushort(__float2bfloat16(b - __bfloat162float(hb))) << 16);
}
__device__ __forceinline__ uint32_t smem_u32(const void* p) {
    uint32_t a;
    asm("{ .reg .u64 t; cvta.to.shared.u64 t, %1; cvt.u32.u64 %0, t; }" : "=r"(a) : "l"(p));
    return a;
}
__device__ __forceinline__ void mma16816(float* c, const uint32_t* a, uint32_t b0, uint32_t b1) {
    asm volatile(
        "mma.sync.aligned.m16n8k16.row.col.f32.bf16.bf16.f32 "
        "{%0,%1,%2,%3}, {%4,%5,%6,%7}, {%8,%9}, {%0,%1,%2,%3};"
        : "+f"(c[0]), "+f"(c[1]), "+f"(c[2]), "+f"(c[3])
        : "r"(a[0]), "r"(a[1]), "r"(a[2]), "r"(a[3]), "r"(b0), "r"(b1));
}
#define LDSM_X4(r0, r1, r2, r3, a) \
    asm volatile("ldmatrix.sync.aligned.m8n8.x4.shared.b16 {%0,%1,%2,%3}, [%4];" \
        : "=r"(r0), "=r"(r1), "=r"(r2), "=r"(r3) : "r"(a))
#define CP_ASYNC16(dsm, src) \
    asm volatile("cp.async.cg.shared.global [%0], [%1], 16;" :: "r"(dsm), "l"(src))
#define CP_COMMIT() asm volatile("cp.async.commit_group;" ::: "memory")
#define CP_WAIT(n)  asm volatile("cp.async.wait_group %0;" :: "n"(n) : "memory")

// ---------------- fused preprocessing: film | zero deg | cvt_w | enc ------------
__device__ void film_body(const float* tmp, const float* W1, const float* b1,
                          const float* W2, const float* b2) {
    __shared__ float g1[4 * 64];
    int tid = threadIdx.x;
    float t = tmp[0] * 1e-6f;
    if (tid < 4 * 64) g1[tid] = geluf(t * W1[tid] + b1[tid]);
    __syncthreads();
    for (int idx = tid; idx < 4 * 256; idx += blockDim.x) {
        int i = idx >> 8, j = idx & 255;
        float acc = b2[idx];
        const float* w = W2 + i * 64 * 256 + j;
        const float* g = g1 + i * 64;
        for (int k = 0; k < 64; k++) acc += g[k] * w[k * 256];
        d_gb[idx] = (j < 128) ? (1.0f + acc) : acc;
    }
}
__device__ void zero_body(int b) {
    int i = b * 256 + threadIdx.x;
    if (i < Nn) d_deg[i] = 0;
}
__device__ void cvtw_body(int b, const float* Wl, const float* Wr) {
    int idx = b * 256 + threadIdx.x;
    int pr = idx & 127;
    int n  = (idx >> 7) & 127;
    int io = idx >> 14;
    int c  = 2 * pr;
    int kk = (c < 128) ? c : (c - 128);
    const float* W = ((io & 1) ? Wr : Wl) + (io >> 1) * 16384;
    float va = W[kk * 128 + n];
    float vb = W[(kk + 1) * 128 + n];
    unsigned int pk = (c < 128) ? pack_hi(va, vb) : pack_lo(va, vb);
    *(unsigned int*)(d_Bw + (size_t)io * 65536 + ((size_t)n * 256 + c) * 2) = pk;
}
__device__ void enc_body(int b, const float* x, const float* W, const float* bb,
                         const float* g, const float* be) {
    __shared__ float Ws[8 * 128], bs[128], gs[128], bes[128];
    int tid = threadIdx.x;
    for (int i = tid; i < 8 * 128; i += 256) Ws[i] = W[i];
    if (tid < 128) { bs[tid] = bb[tid]; gs[tid] = g[tid]; bes[tid] = be[tid]; }
    __syncthreads();
    int warp = tid >> 5, lane = tid & 31;
    int t = b * 8 + warp;
    if (t >= Nn) return;
    float xv[8];
    #pragma unroll
    for (int k = 0; k < 8; k++) xv[k] = x[t * 8 + k];
    float out[4];
    #pragma unroll
    for (int k = 0; k < 4; k++) {
        int d = 4 * lane + k;
        float acc = bs[d];
        #pragma unroll
        for (int i = 0; i < 8; i++) acc += xv[i] * Ws[i * 128 + d];
        out[k] = acc;
    }
    float s = out[0] + out[1] + out[2] + out[3];
    float mean = wsum(s) * (1.0f / 128.0f);
    float v = 0.f;
    #pragma unroll
    for (int k = 0; k < 4; k++) { float dd = out[k] - mean; v += dd * dd; }
    float var = wsum(v) * (1.0f / 128.0f);
    float r = rsqrtf(var + 1e-5f);
    float hv[4];
    #pragma unroll
    for (int k = 0; k < 4; k++) {
        int d = 4 * lane + k;
        float y = (out[k] - mean) * r * gs[d] + bes[d];
        hv[k] = geluf(y);
    }
    *(float4*)&d_h[(size_t)t * 128 + 4 * lane] = make_float4(hv[0], hv[1], hv[2], hv[3]);
    uint2 hp = make_uint2(pack_hi(hv[0], hv[1]), pack_hi(hv[2], hv[3]));
    uint2 lp = make_uint2(pack_lo(hv[0], hv[1]), pack_lo(hv[2], hv[3]));
    *(uint2*)(d_hA + (size_t)t * 512 + 8 * lane)       = hp;
    *(uint2*)(d_hA + (size_t)t * 512 + 256 + 8 * lane) = lp;
}
__global__ void k_pre(const float* tmp, const float* fW1, const float* fb1,
                      const float* fW2, const float* fb2,
                      const float* Wl, const float* Wr,
                      const float* x, const float* encW, const float* encb,
                      const float* encg, const float* encbe) {
    int b = blockIdx.x;
    if (b == 0)            film_body(tmp, fW1, fb1, fW2, fb2);
    else if (b < 197)      zero_body(b - 1);
    else if (b < 709)      cvtw_body(b - 197, Wl, Wr);
    else                   enc_body(b - 709, x, encW, encb, encg, encbe);
}

// ---------------- degree ----------------
__global__ void k_deg(const int* ei) {
    int j = blockIdx.x * blockDim.x + threadIdx.x;
    if (j >= Ee) return;
    atomicAdd(&d_deg[ei[Ee + j]], 1);
}

// ---------------- scan -> CSR row_ptr (counts = deg+1 self loop) ----------------
__global__ void k_scan1() {
    __shared__ int sh[1024];
    int i = blockIdx.x * 1024 + threadIdx.x;
    int v = (i < Nn) ? (d_deg[i] + 1) : 0;
    sh[threadIdx.x] = v;
    __syncthreads();
    for (int off = 1; off < 1024; off <<= 1) {
        int tv = (threadIdx.x >= off) ? sh[threadIdx.x - off] : 0;
        __syncthreads();
        sh[threadIdx.x] += tv;
        __syncthreads();
    }
    if (i < Nn) d_inc[i] = sh[threadIdx.x];
    if (threadIdx.x == 1023) d_bsum[blockIdx.x] = sh[1023];
}
__global__ void k_scan23() {
    __shared__ int base;
    int b = blockIdx.x;
    if (threadIdx.x == 0) {
        int run = 0, grp = b >> 2;
        for (int j = 0; j < grp; j++) run += d_bsum[j];
        base = run;
    }
    __syncthreads();
    int i = b * 256 + threadIdx.x;
    if (i >= Nn) return;
    int val = d_inc[i] + base;
    d_rowptr[i + 1] = val;
    if (i + 1 < Nn) d_cursor[i + 1] = val;
    if (i == 0) { d_rowptr[0] = 0; d_cursor[0] = 0; }
}
__global__ void k_fill(const int* ei) {
    int idx = blockIdx.x * blockDim.x + threadIdx.x;
    if (idx >= ENt) return;
    if (idx < Ee) {
        int s = ei[idx], t = ei[Ee + idx];
        int pos = atomicAdd(&d_cursor[t], 1);
        d_cse[pos] = make_int2(s, idx);
    } else {
        int t = idx - Ee;
        int pos = atomicAdd(&d_cursor[t], 1);
        d_cse[pos] = make_int2(t, Ee + t);
    }
}
// self-loop attr = mean of ea over incoming real edges, gathered via CSR (no atomics)
__global__ void k_loopattr(const float* __restrict__ ea) {
    int t = blockIdx.x * blockDim.x + threadIdx.x;
    if (t >= Nn) return;
    int beg = d_rowptr[t], end = d_rowptr[t + 1];
    float s0 = 0.f, s1 = 0.f, s2 = 0.f, s3 = 0.f;
    for (int p = beg; p < end; p++) {
        int2 se = d_cse[p];
        if (se.y < Ee) {
            float4 a = *(const float4*)&ea[(size_t)se.y * 4];
            s0 += a.x; s1 += a.y; s2 += a.z; s3 += a.w;
        }
    }
    float inv = 1.0f / fmaxf((float)(end - beg - 1), 1.0f);
    d_loop_attr[t * 4 + 0] = s0 * inv;
    d_loop_attr[t * 4 + 1] = s1 * inv;
    d_loop_attr[t * 4 + 2] = s2 * inv;
    d_loop_attr[t * 4 + 3] = s3 * inv;
}

// ---------------- GEMM via mma.sync + ldmatrix, fused 3-product K pass ----------
__global__ void __launch_bounds__(256, 2) k_mma(int layer, const float* __restrict__ bl,
                                                const float* __restrict__ br) {
    extern __shared__ char sm[];
    int tid = threadIdx.x;
    int wid = tid >> 5, lane = tid & 31;
    int wm = wid & 3, wn = wid >> 2;
    int g = lane >> 2, tg = lane & 3;
    const unsigned char* gA = d_hA + (size_t)blockIdx.x * 65536;
    const unsigned char* gB = d_Bw + (size_t)(layer * 2 + blockIdx.y) * 65536;
    // per-lane ldmatrix address offset: row = (lane&7)+(lane&8), colsel = (lane>>4)*8 cols
    uint32_t off_lane = (uint32_t)(((lane & 7) + (lane & 8)) * 80 + ((lane >> 4) << 4));
    uint32_t sbase = smem_u32(sm);

    float acc[2][8][4];
    #pragma unroll
    for (int i = 0; i < 2; i++)
        #pragma unroll
        for (int j = 0; j < 8; j++)
            #pragma unroll
            for (int q = 0; q < 4; q++) acc[i][j][q] = 0.f;

    int lrow0 = tid >> 2, lkq = tid & 3;
    int lrow1 = (tid + 256) >> 2;
    #define STAGE_LOAD(kc, s) do {                                                        \
        char* base_ = sm + (s) * SMSTG;                                                    \
        _Pragma("unroll")                                                                  \
        for (int half_ = 0; half_ < 2; half_++) {                                          \
            const unsigned char* gsrc_ = half_ ? gB : gA;                                  \
            char* dsth_ = base_ + half_ * 20480;                                           \
            _Pragma("unroll")                                                              \
            for (int sub_ = 0; sub_ < 2; sub_++) {                                         \
                const unsigned char* s0_ = gsrc_ + ((size_t)lrow0 * 256 + sub_ * 128 +     \
                                                    (kc) * 32 + lkq * 8) * 2;              \
                const unsigned char* s1_ = gsrc_ + ((size_t)lrow1 * 256 + sub_ * 128 +     \
                                                    (kc) * 32 + lkq * 8) * 2;              \
                uint32_t d0_ = smem_u32(dsth_ + sub_ * 10240 + lrow0 * 80 + lkq * 16);     \
                uint32_t d1_ = smem_u32(dsth_ + sub_ * 10240 + lrow1 * 80 + lkq * 16);     \
                CP_ASYNC16(d0_, s0_);                                                      \
                CP_ASYNC16(d1_, s1_);                                                      \
            }                                                                              \
        }                                                                                  \
    } while (0)

    STAGE_LOAD(0, 0);
    CP_COMMIT();

    #pragma unroll
    for (int kc = 0; kc < 4; kc++) {
        int s = kc & 1;
        if (kc < 3) { STAGE_LOAD(kc + 1, s ^ 1); CP_COMMIT(); }
        if (kc < 3) { CP_WAIT(1); } else { CP_WAIT(0); }
        __syncthreads();
        uint32_t sA = sbase + s * SMSTG;          // Ah; Al=+10240; Bh=+20480; Bl=+30720
        #pragma unroll
        for (int kh = 0; kh < 2; kh++) {
            uint32_t kOff = kh * 32 + off_lane;
            uint32_t ah[2][4], al[2][4];
            #pragma unroll
            for (int mf = 0; mf < 2; mf++) {
                uint32_t rbase = (uint32_t)((wm * 32 + mf * 16) * 80);
                LDSM_X4(ah[mf][0], ah[mf][1], ah[mf][2], ah[mf][3], sA + rbase + kOff);
                LDSM_X4(al[mf][0], al[mf][1], al[mf][2], al[mf][3],
                        sA + 10240 + rbase + kOff);
            }
            #pragma unroll
            for (int np = 0; np < 4; np++) {
                uint32_t nbase = (uint32_t)((wn * 64 + np * 16) * 80);
                uint32_t bh[4], blo[4];
                LDSM_X4(bh[0], bh[1], bh[2], bh[3], sA + 20480 + nbase + kOff);
                LDSM_X4(blo[0], blo[1], blo[2], blo[3], sA + 30720 + nbase + kOff);
                int ne = 2 * np, no = ne + 1;
                mma16816(acc[0][ne], ah[0], bh[0], bh[2]);
                mma16816(acc[1][ne], ah[1], bh[0], bh[2]);
                mma16816(acc[0][no], ah[0], bh[1], bh[3]);
                mma16816(acc[1][no], ah[1], bh[1], bh[3]);
                mma16816(acc[0][ne], ah[0], blo[0], blo[2]);
                mma16816(acc[1][ne], ah[1], blo[0], blo[2]);
                mma16816(acc[0][no], ah[0], blo[1], blo[3]);
                mma16816(acc[1][no], ah[1], blo[1], blo[3]);
                mma16816(acc[0][ne], al[0], bh[0], bh[2]);
                mma16816(acc[1][ne], al[1], bh[0], bh[2]);
                mma16816(acc[0][no], al[0], bh[1], bh[3]);
                mma16816(acc[1][no], al[1], bh[1], bh[3]);
            }
        }
        __syncthreads();
    }

    const float* bias = blockIdx.y ? br : bl;
    float* dst = blockIdx.y ? d_xr : d_xl;
    #pragma unroll
    for (int mf = 0; mf < 2; mf++) {
        #pragma unroll
        for (int nf = 0; nf < 8; nf++) {
            int m = blockIdx.x * 128 + wm * 32 + mf * 16;
            int col = wn * 64 + nf * 8 + tg * 2;
            float bx = bias[col], by = bias[col + 1];
            int r0 = m + g, r1 = m + g + 8;
            if (r0 < Nn) {
                float2 o = make_float2(acc[mf][nf][0] + bx, acc[mf][nf][1] + by);
                *(float2*)&dst[(size_t)r0 * 128 + col] = o;
            }
            if (r1 < Nn) {
                float2 o = make_float2(acc[mf][nf][2] + bx, acc[mf][nf][3] + by);
                *(float2*)&dst[(size_t)r1 * 128 + col] = o;
            }
        }
    }
}

// ---- fused GATv2 (batch-4 online softmax, cse prefetch) + LN + FiLM + residual --
__global__ void k_gat(const float* __restrict__ ea, const float* __restrict__ We,
                      const float* __restrict__ att, const float* __restrict__ cb,
                      const float* __restrict__ lng, const float* __restrict__ lnb,
                      int layer) {
    int tid = threadIdx.x, l = tid & 31;
    int t = blockIdx.x * 8 + (tid >> 5);
    if (t >= Nn) return;
    int beg = d_rowptr[t], end = d_rowptr[t + 1];
    float4 xr4 = *(const float4*)&d_xr[(size_t)t * 128 + 4 * l];
    float4 at4 = *(const float4*)&att[4 * l];
    float4 we0 = *(const float4*)&We[0 * 128 + 4 * l];
    float4 we1 = *(const float4*)&We[1 * 128 + 4 * l];
    float4 we2 = *(const float4*)&We[2 * 128 + 4 * l];
    float4 we3 = *(const float4*)&We[3 * 128 + 4 * l];

    float M = -3.4e38f, S = 0.f;
    float a0 = 0.f, a1 = 0.f, a2 = 0.f, a3 = 0.f;

    #define EDGE_PRE(se, x4, sc) {                                                         \
        const float* eap_ = (se.y < Ee) ? (ea + (size_t)se.y * 4)                          \
                                        : (d_loop_attr + (size_t)(se.y - Ee) * 4);         \
        float4 a4_ = *(const float4*)eap_;                                                 \
        x4 = *(const float4*)&d_xl[(size_t)se.x * 128 + 4 * l];                            \
        float m0 = x4.x + xr4.x + a4_.x * we0.x + a4_.y * we1.x + a4_.z * we2.x + a4_.w * we3.x; \
        float m1 = x4.y + xr4.y + a4_.x * we0.y + a4_.y * we1.y + a4_.z * we2.y + a4_.w * we3.y; \
        float m2 = x4.z + xr4.z + a4_.x * we0.z + a4_.y * we1.z + a4_.z * we2.z + a4_.w * we3.z; \
        float m3 = x4.w + xr4.w + a4_.x * we0.w + a4_.y * we1.w + a4_.z * we2.w + a4_.w * we3.w; \
        m0 = (m0 > 0.f) ? m0 : 0.2f * m0;                                                  \
        m1 = (m1 > 0.f) ? m1 : 0.2f * m1;                                                  \
        m2 = (m2 > 0.f) ? m2 : 0.2f * m2;                                                  \
        m3 = (m3 > 0.f) ? m3 : 0.2f * m3;                                                  \
        sc = m0 * at4.x + m1 * at4.y + m2 * at4.z + m3 * at4.w;                            \
    }

    int p = beg;
    int2 pse0, pse1, pse2, pse3;
    if (p + 4 <= end) {
        pse0 = d_cse[p];     pse1 = d_cse[p + 1];
        pse2 = d_cse[p + 2]; pse3 = d_cse[p + 3];
    }
    while (p + 4 <= end) {
        int2 se0 = pse0, se1 = pse1, se2 = pse2, se3 = pse3;
        int pn = p + 4;
        if (pn + 4 <= end) {       // prefetch next batch's indices early
            pse0 = d_cse[pn];     pse1 = d_cse[pn + 1];
            pse2 = d_cse[pn + 2]; pse3 = d_cse[pn + 3];
        }
        float4 x0, x1, x2, x3;
        float sc0, sc1, sc2, sc3;
        EDGE_PRE(se0, x0, sc0);
        EDGE_PRE(se1, x1, sc1);
        EDGE_PRE(se2, x2, sc2);
        EDGE_PRE(se3, x3, sc3);
        sc0 += __shfl_xor_sync(0xffffffffu, sc0, 1);
        sc1 += __shfl_xor_sync(0xffffffffu, sc1, 1);
        sc2 += __shfl_xor_sync(0xffffffffu, sc2, 1);
        sc3 += __shfl_xor_sync(0xffffffffu, sc3, 1);
        sc0 += __shfl_xor_sync(0xffffffffu, sc0, 2);
        sc1 += __shfl_xor_sync(0xffffffffu, sc1, 2);
        sc2 += __shfl_xor_sync(0xffffffffu, sc2, 2);
        sc3 += __shfl_xor_sync(0xffffffffu, sc3, 2);
        sc0 += __shfl_xor_sync(0xffffffffu, sc0, 4);
        sc1 += __shfl_xor_sync(0xffffffffu, sc1, 4);
        sc2 += __shfl_xor_sync(0xffffffffu, sc2, 4);
        sc3 += __shfl_xor_sync(0xffffffffu, sc3, 4);
        float nM = fmaxf(M, fmaxf(fmaxf(sc0, sc1), fmaxf(sc2, sc3)));
        float corr = __expf(M - nM);
        float w0 = __expf(sc0 - nM), w1 = __expf(sc1 - nM);
        float w2 = __expf(sc2 - nM), w3 = __expf(sc3 - nM);
        S = S * corr + ((w0 + w1) + (w2 + w3));
        a0 = a0 * corr + (w0 * x0.x + w1 * x1.x) + (w2 * x2.x + w3 * x3.x);
        a1 = a1 * corr + (w0 * x0.y + w1 * x1.y) + (w2 * x2.y + w3 * x3.y);
        a2 = a2 * corr + (w0 * x0.z + w1 * x1.z) + (w2 * x2.z + w3 * x3.z);
        a3 = a3 * corr + (w0 * x0.w + w1 * x1.w) + (w2 * x2.w + w3 * x3.w);
        M = nM;
        p = pn;
    }
    for (; p < end; p++) {
        int2 se = d_cse[p];
        float4 x0;
        float sc;
        EDGE_PRE(se, x0, sc);
        sc += __shfl_xor_sync(0xffffffffu, sc, 1);
        sc += __shfl_xor_sync(0xffffffffu, sc, 2);
        sc += __shfl_xor_sync(0xffffffffu, sc, 4);
        float nM = fmaxf(M, sc);
        float corr = __expf(M - nM);
        float w = __expf(sc - nM);
        S = S * corr + w;
        a0 = a0 * corr + w * x0.x;
        a1 = a1 * corr + w * x0.y;
        a2 = a2 * corr + w * x0.z;
        a3 = a3 * corr + w * x0.w;
        M = nM;
    }
    float inv = 1.0f / (S + 1e-16f);
    float4 cb4 = *(const float4*)&cb[4 * l];
    float hc0 = a0 * inv + cb4.x;
    float hc1 = a1 * inv + cb4.y;
    float hc2 = a2 * inv + cb4.z;
    float hc3 = a3 * inv + cb4.w;

    // fused post: LN + FiLM + GELU + residual
    float mean = wsum(hc0 + hc1 + hc2 + hc3) * (1.0f / 128.0f);
    float v0 = hc0 - mean, v1 = hc1 - mean, v2 = hc2 - mean, v3 = hc3 - mean;
    float var = wsum(v0 * v0 + v1 * v1 + v2 * v2 + v3 * v3) * (1.0f / 128.0f);
    float r = rsqrtf(var + 1e-5f);
    float4 lg4 = *(const float4*)&lng[4 * l];
    float4 lb4 = *(const float4*)&lnb[4 * l];
    float4 gm4 = *(const float4*)&d_gb[layer * 256 + 4 * l];
    float4 bt4 = *(const float4*)&d_gb[layer * 256 + 128 + 4 * l];
    float4 hold = *(const float4*)&d_h[(size_t)t * 128 + 4 * l];
    float h0 = geluf(gm4.x * (v0 * r * lg4.x + lb4.x) + bt4.x) + hold.x;
    float h1 = geluf(gm4.y * (v1 * r * lg4.y + lb4.y) + bt4.y) + hold.y;
    float h2 = geluf(gm4.z * (v2 * r * lg4.z + lb4.z) + bt4.z) + hold.z;
    float h3 = geluf(gm4.w * (v3 * r * lg4.w + lb4.w) + bt4.w) + hold.w;
    *(float4*)&d_h[(size_t)t * 128 + 4 * l] = make_float4(h0, h1, h2, h3);
    if (layer < 3) {
        uint2 hp = make_uint2(pack_hi(h0, h1), pack_hi(h2, h3));
        uint2 lp = make_uint2(pack_lo(h0, h1), pack_lo(h2, h3));
        *(uint2*)(d_hA + (size_t)t * 512 + 8 * l)       = hp;
        *(uint2*)(d_hA + (size_t)t * 512 + 256 + 8 * l) = lp;
    }
}

// ---------------- decoder + masks + nc/delta write ----------------
__global__ void k_dec(const float* x, const unsigned char* fx, const unsigned char* fy,
                      const float* W1, const float* b1, const float* W2, const float* b2,
                      float* out) {
    __shared__ float W1s[128 * 64];
    __shared__ float W2s[128];
    __shared__ float b1s[64];
    __shared__ float b2s[2];
    __shared__ float hs[8][128];
    int tid = threadIdx.x;
    for (int i = tid; i < 128 * 64; i += 256) W1s[i] = W1[i];
    if (tid < 128) W2s[tid] = W2[tid];
    if (tid < 64) b1s[tid] = b1[tid];
    if (tid < 2) b2s[tid] = b2[tid];
    int warp = tid >> 5, lane = tid & 31;
    int t = blockIdx.x * 8 + warp;
    if (t < Nn) {
        #pragma unroll
        for (int k = 0; k < 4; k++) hs[warp][lane + 32 * k] = d_h[t * 128 + lane + 32 * k];
    }
    __syncthreads();
    if (t >= Nn) return;
    int j1 = lane, j2 = lane + 32;
    float t1a = b1s[j1], t1b = b1s[j2];
    #pragma unroll 8
    for (int k = 0; k < 128; k++) {
        float hk = hs[warp][k];
        t1a += hk * W1s[k * 64 + j1];
        t1b += hk * W1s[k * 64 + j2];
    }
    float g1a = geluf(t1a), g1b = geluf(t1b);
    float dc0 = wsum(g1a * W2s[j1 * 2 + 0] + g1b * W2s[j2 * 2 + 0]);
    float dc1 = wsum(g1a * W2s[j1 * 2 + 1] + g1b * W2s[j2 * 2 + 1]);
    if (lane == 0) {
        dc0 += b2s[0]; dc1 += b2s[1];
        dc0 = fminf(fmaxf(dc0, -50.f), 50.f);
        dc1 = fminf(fmaxf(dc1, -50.f), 50.f);
        float dx = fx[t] ? 0.f : dc0;
        float dy = fy[t] ? 0.f : dc1;
        out[t * 2 + 0] = x[t * 8 + 0] + dx;
        out[t * 2 + 1] = x[t * 8 + 1] + dy;
        out[2 * Nn + t * 2 + 0] = dx;
        out[2 * Nn + t * 2 + 1] = dy;
    }
}

// ------------- join pairs fused: tag / mid / scatter in ONE block ---------------
__global__ void __launch_bounds__(1024, 1) k_joinall(const int* jp, float* out) {
    int j = threadIdx.x;
    int u = jp[j * 2 + 0], v = jp[j * 2 + 1];
    d_tag[u] = -1;
    d_tag[v] = -1;
    __syncthreads();
    float mx = (out[u * 2 + 0] + out[v * 2 + 0]) * 0.5f;
    float my = (out[u * 2 + 1] + out[v * 2 + 1]) * 0.5f;
    atomicMax(&d_tag[u], j);
    atomicMax(&d_tag[v], Pp + j);
    __syncthreads();
    if (d_tag[u] == j) {
        out[u * 2 + 0] = mx;
        out[u * 2 + 1] = my;
    }
    if (d_tag[v] == Pp + j) {
        out[v * 2 + 0] = mx;
        out[v * 2 + 1] = my;
    }
}

// ---------------- launch ----------------
extern "C" void kernel_launch(void* const* d_in, const int* in_sizes, int n_in,
                              void* d_out, int out_size) {
    const float* x      = (const float*)d_in[0];
    const int*   ei     = (const int*)  d_in[1];
    const float* ea     = (const float*)d_in[2];
    const float* tmp    = (const float*)d_in[3];
    const unsigned char* fxm = (const unsigned char*)d_in[4];
    const unsigned char* fym = (const unsigned char*)d_in[5];
    const int*   jp     = (const int*)  d_in[6];
    const float* encW   = (const float*)d_in[7];
    const float* encb   = (const float*)d_in[8];
    const float* encg   = (const float*)d_in[9];
    const float* encbe  = (const float*)d_in[10];
    const float* fW1    = (const float*)d_in[11];
    const float* fb1    = (const float*)d_in[12];
    const float* fW2    = (const float*)d_in[13];
    const float* fb2    = (const float*)d_in[14];
    const float* Wl     = (const float*)d_in[15];
    const float* bl     = (const float*)d_in[16];
    const float* Wr     = (const float*)d_in[17];
    const float* br     = (const float*)d_in[18];
    const float* We     = (const float*)d_in[19];
    const float* att    = (const float*)d_in[20];
    const float* cb     = (const float*)d_in[21];
    const float* lng    = (const float*)d_in[22];
    const float* lnb    = (const float*)d_in[23];
    const float* dW1    = (const float*)d_in[24];
    const float* db1    = (const float*)d_in[25];
    const float* dW2    = (const float*)d_in[26];
    const float* db2    = (const float*)d_in[27];
    float* out = (float*)d_out;

    cudaFuncSetAttribute(k_mma, cudaFuncAttributeMaxDynamicSharedMemorySize, 2 * SMSTG);

    k_pre<<<709 + (Nn + 7) / 8, 256>>>(tmp, fW1, fb1, fW2, fb2, Wl, Wr,
                                       x, encW, encb, encg, encbe);
    k_deg<<<(Ee + 255) / 256, 256>>>(ei);
    k_scan1<<<NBS, 1024>>>();
    k_scan23<<<(Nn + 255) / 256, 256>>>();
    k_fill<<<(ENt + 255) / 256, 256>>>(ei);
    k_loopattr<<<(Nn + 255) / 256, 256>>>(ea);
    for (int i = 0; i < 4; i++) {
        k_mma<<<dim3(NT, 2), 256, 2 * SMSTG>>>(i, bl + i * 128, br + i * 128);
        k_gat<<<(Nn + 7) / 8, 256>>>(ea, We + i * 4 * 128, att + i * 128, cb + i * 128,
                                     lng + i * 128, lnb + i * 128, i);
    }
    k_dec<<<(Nn + 7) / 8, 256>>>(x, fxm, fym, dW1, db1, dW2, db2, out);
    k_joinall<<<1, 1024>>>(jp, out);
}

// round 14
// speedup vs baseline: 1.1538x; 1.1538x over previous
#include <cuda_runtime.h>
#include <cuda_bf16.h>
#include <math.h>
#include <stdint.h>

// Problem constants (fixed by the dataset)
#define Nn   50000
#define Ee   640000
#define Pp   1024
#define ENt  (Ee + Nn)          // edges + self loops
#define NBS  49                 // ceil(N/1024) scan blocks
#define NT   391                // ceil(N/128) M tiles
#define SMSTG 40960             // bytes per k_mma pipeline stage

// ---------------- device scratch (no allocations allowed) ----------------
__device__ __align__(16) float d_h [Nn * 128];
__device__ __align__(16) float d_xl[Nn * 128];
__device__ __align__(16) float d_xr[Nn * 128];
__device__ __align__(16) float d_loop_attr[Nn * 4];
__device__ int   d_deg[Nn];
__device__ int   d_inc[Nn];
__device__ int   d_bsum[64];
__device__ int   d_rowptr[Nn + 1];
__device__ int   d_cursor[Nn];
__device__ __align__(16) int2 d_cse[ENt];          // (src, eid) packed
__device__ float d_gb[4 * 256];                    // per-layer gamma(128)/beta(128)
__device__ int   d_tag[Nn];
// bf16 hi/lo row-major MMA operand images
__device__ __align__(16) unsigned char d_hA[(size_t)NT * 65536];
__device__ __align__(16) unsigned char d_Bw[8 * 65536];

// ---------------- generic helpers ----------------
__device__ __forceinline__ float geluf(float v) {
    return 0.5f * v * (1.0f + erff(v * 0.70710678118654752440f));
}
__device__ __forceinline__ float wsum(float v) {
    #pragma unroll
    for (int o = 16; o > 0; o >>= 1) v += __shfl_xor_sync(0xffffffffu, v, o);
    return v;
}
__device__ __forceinline__ unsigned int pack_hi(float a, float b) {
    return (unsigned int)__bfloat16_as_ushort(__float2bfloat16(a)) |
           ((unsigned int)__bfloat16_as_ushort(__float2bfloat16(b)) << 16);
}
__device__ __forceinline__ unsigned int pack_lo(float a, float b) {
    __nv_bfloat16 ha = __float2bfloat16(a), hb = __float2bfloat16(b);
    return (unsigned int)__bfloat16_as_ushort(__float2bfloat16(a - __bfloat162float(ha))) |
           ((unsigned int)__bfloat16_as_ushort(__float2bfloat16(b - __bfloat162float(hb))) << 16);
}
__device__ __forceinline__ uint32_t smem_u32(const void* p) {
    uint32_t a;
    asm("{ .reg .u64 t; cvta.to.shared.u64 t, %1; cvt.u32.u64 %0, t; }" : "=r"(a) : "l"(p));
    return a;
}
__device__ __forceinline__ void mma16816(float* c, const uint32_t* a, uint32_t b0, uint32_t b1) {
    asm volatile(
        "mma.sync.aligned.m16n8k16.row.col.f32.bf16.bf16.f32 "
        "{%0,%1,%2,%3}, {%4,%5,%6,%7}, {%8,%9}, {%0,%1,%2,%3};"
        : "+f"(c[0]), "+f"(c[1]), "+f"(c[2]), "+f"(c[3])
        : "r"(a[0]), "r"(a[1]), "r"(a[2]), "r"(a[3]), "r"(b0), "r"(b1));
}
#define CP_ASYNC16(dsm, src) \
    asm volatile("cp.async.cg.shared.global [%0], [%1], 16;" :: "r"(dsm), "l"(src))
#define CP_COMMIT() asm volatile("cp.async.commit_group;" ::: "memory")
#define CP_WAIT(n)  asm volatile("cp.async.wait_group %0;" :: "n"(n) : "memory")

// ---------------- fused preprocessing: film | zero deg | cvt_w | enc ------------
__device__ void film_body(const float* tmp, const float* W1, const float* b1,
                          const float* W2, const float* b2) {
    __shared__ float g1[4 * 64];
    int tid = threadIdx.x;
    float t = tmp[0] * 1e-6f;
    if (tid < 4 * 64) g1[tid] = geluf(t * W1[tid] + b1[tid]);
    __syncthreads();
    for (int idx = tid; idx < 4 * 256; idx += blockDim.x) {
        int i = idx >> 8, j = idx & 255;
        float acc = b2[idx];
        const float* w = W2 + i * 64 * 256 + j;
        const float* g = g1 + i * 64;
        for (int k = 0; k < 64; k++) acc += g[k] * w[k * 256];
        d_gb[idx] = (j < 128) ? (1.0f + acc) : acc;
    }
}
__device__ void zero_body(int b) {
    int i = b * 256 + threadIdx.x;
    if (i < Nn) d_deg[i] = 0;
}
__device__ void cvtw_body(int b, const float* Wl, const float* Wr) {
    int idx = b * 256 + threadIdx.x;
    int pr = idx & 127;
    int n  = (idx >> 7) & 127;
    int io = idx >> 14;
    int c  = 2 * pr;
    int kk = (c < 128) ? c : (c - 128);
    const float* W = ((io & 1) ? Wr : Wl) + (io >> 1) * 16384;
    float va = W[kk * 128 + n];
    float vb = W[(kk + 1) * 128 + n];
    unsigned int pk = (c < 128) ? pack_hi(va, vb) : pack_lo(va, vb);
    *(unsigned int*)(d_Bw + (size_t)io * 65536 + ((size_t)n * 256 + c) * 2) = pk;
}
__device__ void enc_body(int b, const float* x, const float* W, const float* bb,
                         const float* g, const float* be) {
    __shared__ float Ws[8 * 128], bs[128], gs[128], bes[128];
    int tid = threadIdx.x;
    for (int i = tid; i < 8 * 128; i += 256) Ws[i] = W[i];
    if (tid < 128) { bs[tid] = bb[tid]; gs[tid] = g[tid]; bes[tid] = be[tid]; }
    __syncthreads();
    int warp = tid >> 5, lane = tid & 31;
    int t = b * 8 + warp;
    if (t >= Nn) return;
    float xv[8];
    #pragma unroll
    for (int k = 0; k < 8; k++) xv[k] = x[t * 8 + k];
    float out[4];
    #pragma unroll
    for (int k = 0; k < 4; k++) {
        int d = 4 * lane + k;
        float acc = bs[d];
        #pragma unroll
        for (int i = 0; i < 8; i++) acc += xv[i] * Ws[i * 128 + d];
        out[k] = acc;
    }
    float s = out[0] + out[1] + out[2] + out[3];
    float mean = wsum(s) * (1.0f / 128.0f);
    float v = 0.f;
    #pragma unroll
    for (int k = 0; k < 4; k++) { float dd = out[k] - mean; v += dd * dd; }
    float var = wsum(v) * (1.0f / 128.0f);
    float r = rsqrtf(var + 1e-5f);
    float hv[4];
    #pragma unroll
    for (int k = 0; k < 4; k++) {
        int d = 4 * lane + k;
        float y = (out[k] - mean) * r * gs[d] + bes[d];
        hv[k] = geluf(y);
    }
    *(float4*)&d_h[(size_t)t * 128 + 4 * lane] = make_float4(hv[0], hv[1], hv[2], hv[3]);
    uint2 hp = make_uint2(pack_hi(hv[0], hv[1]), pack_hi(hv[2], hv[3]));
    uint2 lp = make_uint2(pack_lo(hv[0], hv[1]), pack_lo(hv[2], hv[3]));
    *(uint2*)(d_hA + (size_t)t * 512 + 8 * lane)       = hp;
    *(uint2*)(d_hA + (size_t)t * 512 + 256 + 8 * lane) = lp;
}
__global__ void k_pre(const float* tmp, const float* fW1, const float* fb1,
                      const float* fW2, const float* fb2,
                      const float* Wl, const float* Wr,
                      const float* x, const float* encW, const float* encb,
                      const float* encg, const float* encbe) {
    int b = blockIdx.x;
    if (b == 0)            film_body(tmp, fW1, fb1, fW2, fb2);
    else if (b < 197)      zero_body(b - 1);
    else if (b < 709)      cvtw_body(b - 197, Wl, Wr);
    else                   enc_body(b - 709, x, encW, encb, encg, encbe);
}

// ---------------- degree ----------------
__global__ void k_deg(const int* ei) {
    int j = blockIdx.x * blockDim.x + threadIdx.x;
    if (j >= Ee) return;
    atomicAdd(&d_deg[ei[Ee + j]], 1);
}

// ---------------- scan -> CSR row_ptr (counts = deg+1 self loop) ----------------
__global__ void k_scan1() {
    __shared__ int sh[1024];
    int i = blockIdx.x * 1024 + threadIdx.x;
    int v = (i < Nn) ? (d_deg[i] + 1) : 0;
    sh[threadIdx.x] = v;
    __syncthreads();
    for (int off = 1; off < 1024; off <<= 1) {
        int tv = (threadIdx.x >= off) ? sh[threadIdx.x - off] : 0;
        __syncthreads();
        sh[threadIdx.x] += tv;
        __syncthreads();
    }
    if (i < Nn) d_inc[i] = sh[threadIdx.x];
    if (threadIdx.x == 1023) d_bsum[blockIdx.x] = sh[1023];
}
__global__ void k_scan23() {
    __shared__ int base;
    int b = blockIdx.x;
    if (threadIdx.x == 0) {
        int run = 0, grp = b >> 2;
        for (int j = 0; j < grp; j++) run += d_bsum[j];
        base = run;
    }
    __syncthreads();
    int i = b * 256 + threadIdx.x;
    if (i >= Nn) return;
    int val = d_inc[i] + base;
    d_rowptr[i + 1] = val;
    if (i + 1 < Nn) d_cursor[i + 1] = val;
    if (i == 0) { d_rowptr[0] = 0; d_cursor[0] = 0; }
}
__global__ void k_fill(const int* ei) {
    int idx = blockIdx.x * blockDim.x + threadIdx.x;
    if (idx >= ENt) return;
    if (idx < Ee) {
        int s = ei[idx], t = ei[Ee + idx];
        int pos = atomicAdd(&d_cursor[t], 1);
        d_cse[pos] = make_int2(s, idx);
    } else {
        int t = idx - Ee;
        int pos = atomicAdd(&d_cursor[t], 1);
        d_cse[pos] = make_int2(t, Ee + t);
    }
}
// self-loop attr = mean of ea over incoming real edges, gathered via CSR (no atomics)
__global__ void k_loopattr(const float* __restrict__ ea) {
    int t = blockIdx.x * blockDim.x + threadIdx.x;
    if (t >= Nn) return;
    int beg = d_rowptr[t], end = d_rowptr[t + 1];
    float s0 = 0.f, s1 = 0.f, s2 = 0.f, s3 = 0.f;
    for (int p = beg; p < end; p++) {
        int2 se = d_cse[p];
        if (se.y < Ee) {
            float4 a = *(const float4*)&ea[(size_t)se.y * 4];
            s0 += a.x; s1 += a.y; s2 += a.z; s3 += a.w;
        }
    }
    float inv = 1.0f / fmaxf((float)(end - beg - 1), 1.0f);
    d_loop_attr[t * 4 + 0] = s0 * inv;
    d_loop_attr[t * 4 + 1] = s1 * inv;
    d_loop_attr[t * 4 + 2] = s2 * inv;
    d_loop_attr[t * 4 + 3] = s3 * inv;
}

// ---------------- GEMM via mma.sync, fused 3-product K pass + cp.async pipe -----
// (R12 version — scalar LDS operand loads; ptxas schedules them freely)
__global__ void __launch_bounds__(256, 2) k_mma(int layer, const float* __restrict__ bl,
                                                const float* __restrict__ br) {
    extern __shared__ char sm[];
    int tid = threadIdx.x;
    int wid = tid >> 5, lane = tid & 31;
    int wm = wid & 3, wn = wid >> 2;
    int g = lane >> 2, tg = lane & 3;
    const unsigned char* gA = d_hA + (size_t)blockIdx.x * 65536;
    const unsigned char* gB = d_Bw + (size_t)(layer * 2 + blockIdx.y) * 65536;

    float acc[2][8][4];
    #pragma unroll
    for (int i = 0; i < 2; i++)
        #pragma unroll
        for (int j = 0; j < 8; j++)
            #pragma unroll
            for (int q = 0; q < 4; q++) acc[i][j][q] = 0.f;

    int lrow0 = tid >> 2, lkq = tid & 3;
    int lrow1 = (tid + 256) >> 2;
    #define STAGE_LOAD(kc, s) do {                                                        \
        char* base_ = sm + (s) * SMSTG;                                                    \
        _Pragma("unroll")                                                                  \
        for (int half_ = 0; half_ < 2; half_++) {                                          \
            const unsigned char* gsrc_ = half_ ? gB : gA;                                  \
            char* dsth_ = base_ + half_ * 20480;                                           \
            _Pragma("unroll")                                                              \
            for (int sub_ = 0; sub_ < 2; sub_++) {                                         \
                const unsigned char* s0_ = gsrc_ + ((size_t)lrow0 * 256 + sub_ * 128 +     \
                                                    (kc) * 32 + lkq * 8) * 2;              \
                const unsigned char* s1_ = gsrc_ + ((size_t)lrow1 * 256 + sub_ * 128 +     \
                                                    (kc) * 32 + lkq * 8) * 2;              \
                uint32_t d0_ = smem_u32(dsth_ + sub_ * 10240 + lrow0 * 80 + lkq * 16);     \
                uint32_t d1_ = smem_u32(dsth_ + sub_ * 10240 + lrow1 * 80 + lkq * 16);     \
                CP_ASYNC16(d0_, s0_);                                                      \
                CP_ASYNC16(d1_, s1_);                                                      \
            }                                                                              \
        }                                                                                  \
    } while (0)

    STAGE_LOAD(0, 0);
    CP_COMMIT();

    #pragma unroll
    for (int kc = 0; kc < 4; kc++) {
        int s = kc & 1;
        if (kc < 3) { STAGE_LOAD(kc + 1, s ^ 1); CP_COMMIT(); }
        if (kc < 3) { CP_WAIT(1); } else { CP_WAIT(0); }
        __syncthreads();
        const char* Ah = sm + s * SMSTG;
        const char* Al = Ah + 10240;
        const char* Bh = Ah + 20480;
        const char* Bl = Ah + 30720;
        #pragma unroll
        for (int kh = 0; kh < 2; kh++) {
            int kb = (kh * 16 + tg * 2) * 2;
            uint32_t ah[2][4], al[2][4];
            #pragma unroll
            for (int mf = 0; mf < 2; mf++) {
                int m0 = wm * 32 + mf * 16;
                ah[mf][0] = *(const uint32_t*)(Ah + (m0 + g) * 80 + kb);
                ah[mf][1] = *(const uint32_t*)(Ah + (m0 + g + 8) * 80 + kb);
                ah[mf][2] = *(const uint32_t*)(Ah + (m0 + g) * 80 + kb + 16);
                ah[mf][3] = *(const uint32_t*)(Ah + (m0 + g + 8) * 80 + kb + 16);
                al[mf][0] = *(const uint32_t*)(Al + (m0 + g) * 80 + kb);
                al[mf][1] = *(const uint32_t*)(Al + (m0 + g + 8) * 80 + kb);
                al[mf][2] = *(const uint32_t*)(Al + (m0 + g) * 80 + kb + 16);
                al[mf][3] = *(const uint32_t*)(Al + (m0 + g + 8) * 80 + kb + 16);
            }
            #pragma unroll
            for (int nf = 0; nf < 8; nf++) {
                int n0 = wn * 64 + nf * 8;
                uint32_t bh0 = *(const uint32_t*)(Bh + (n0 + g) * 80 + kb);
                uint32_t bh1 = *(const uint32_t*)(Bh + (n0 + g) * 80 + kb + 16);
                uint32_t bl0 = *(const uint32_t*)(Bl + (n0 + g) * 80 + kb);
                uint32_t bl1 = *(const uint32_t*)(Bl + (n0 + g) * 80 + kb + 16);
                mma16816(acc[0][nf], ah[0], bh0, bh1);
                mma16816(acc[1][nf], ah[1], bh0, bh1);
                mma16816(acc[0][nf], ah[0], bl0, bl1);
                mma16816(acc[1][nf], ah[1], bl0, bl1);
                mma16816(acc[0][nf], al[0], bh0, bh1);
                mma16816(acc[1][nf], al[1], bh0, bh1);
            }
        }
        __syncthreads();
    }

    const float* bias = blockIdx.y ? br : bl;
    float* dst = blockIdx.y ? d_xr : d_xl;
    #pragma unroll
    for (int mf = 0; mf < 2; mf++) {
        #pragma unroll
        for (int nf = 0; nf < 8; nf++) {
            int m = blockIdx.x * 128 + wm * 32 + mf * 16;
            int col = wn * 64 + nf * 8 + tg * 2;
            float bx = bias[col], by = bias[col + 1];
            int r0 = m + g, r1 = m + g + 8;
            if (r0 < Nn) {
                float2 o = make_float2(acc[mf][nf][0] + bx, acc[mf][nf][1] + by);
                *(float2*)&dst[(size_t)r0 * 128 + col] = o;
            }
            if (r1 < Nn) {
                float2 o = make_float2(acc[mf][nf][2] + bx, acc[mf][nf][3] + by);
                *(float2*)&dst[(size_t)r1 * 128 + col] = o;
            }
        }
    }
}

// ---- fused GATv2 (batch-4 online softmax) + LN + FiLM + GELU + residual --------
// (R12 version — no index prefetch)
__global__ void k_gat(const float* __restrict__ ea, const float* __restrict__ We,
                      const float* __restrict__ att, const float* __restrict__ cb,
                      const float* __restrict__ lng, const float* __restrict__ lnb,
                      int layer) {
    int tid = threadIdx.x, l = tid & 31;
    int t = blockIdx.x * 8 + (tid >> 5);
    if (t >= Nn) return;
    int beg = d_rowptr[t], end = d_rowptr[t + 1];
    float4 xr4 = *(const float4*)&d_xr[(size_t)t * 128 + 4 * l];
    float4 at4 = *(const float4*)&att[4 * l];
    float4 we0 = *(const float4*)&We[0 * 128 + 4 * l];
    float4 we1 = *(const float4*)&We[1 * 128 + 4 * l];
    float4 we2 = *(const float4*)&We[2 * 128 + 4 * l];
    float4 we3 = *(const float4*)&We[3 * 128 + 4 * l];

    float M = -3.4e38f, S = 0.f;
    float a0 = 0.f, a1 = 0.f, a2 = 0.f, a3 = 0.f;

    #define EDGE_PRE(se, x4, sc) {                                                         \
        const float* eap_ = (se.y < Ee) ? (ea + (size_t)se.y * 4)                          \
                                        : (d_loop_attr + (size_t)(se.y - Ee) * 4);         \
        float4 a4_ = *(const float4*)eap_;                                                 \
        x4 = *(const float4*)&d_xl[(size_t)se.x * 128 + 4 * l];                            \
        float m0 = x4.x + xr4.x + a4_.x * we0.x + a4_.y * we1.x + a4_.z * we2.x + a4_.w * we3.x; \
        float m1 = x4.y + xr4.y + a4_.x * we0.y + a4_.y * we1.y + a4_.z * we2.y + a4_.w * we3.y; \
        float m2 = x4.z + xr4.z + a4_.x * we0.z + a4_.y * we1.z + a4_.z * we2.z + a4_.w * we3.z; \
        float m3 = x4.w + xr4.w + a4_.x * we0.w + a4_.y * we1.w + a4_.z * we2.w + a4_.w * we3.w; \
        m0 = (m0 > 0.f) ? m0 : 0.2f * m0;                                                  \
        m1 = (m1 > 0.f) ? m1 : 0.2f * m1;                                                  \
        m2 = (m2 > 0.f) ? m2 : 0.2f * m2;                                                  \
        m3 = (m3 > 0.f) ? m3 : 0.2f * m3;                                                  \
        sc = m0 * at4.x + m1 * at4.y + m2 * at4.z + m3 * at4.w;                            \
    }

    int p = beg;
    for (; p + 4 <= end; p += 4) {
        int2 se0 = d_cse[p], se1 = d_cse[p + 1], se2 = d_cse[p + 2], se3 = d_cse[p + 3];
        float4 x0, x1, x2, x3;
        float sc0, sc1, sc2, sc3;
        EDGE_PRE(se0, x0, sc0);
        EDGE_PRE(se1, x1, sc1);
        EDGE_PRE(se2, x2, sc2);
        EDGE_PRE(se3, x3, sc3);
        sc0 += __shfl_xor_sync(0xffffffffu, sc0, 1);
        sc1 += __shfl_xor_sync(0xffffffffu, sc1, 1);
        sc2 += __shfl_xor_sync(0xffffffffu, sc2, 1);
        sc3 += __shfl_xor_sync(0xffffffffu, sc3, 1);
        sc0 += __shfl_xor_sync(0xffffffffu, sc0, 2);
        sc1 += __shfl_xor_sync(0xffffffffu, sc1, 2);
        sc2 += __shfl_xor_sync(0xffffffffu, sc2, 2);
        sc3 += __shfl_xor_sync(0xffffffffu, sc3, 2);
        sc0 += __shfl_xor_sync(0xffffffffu, sc0, 4);
        sc1 += __shfl_xor_sync(0xffffffffu, sc1, 4);
        sc2 += __shfl_xor_sync(0xffffffffu, sc2, 4);
        sc3 += __shfl_xor_sync(0xffffffffu, sc3, 4);
        float nM = fmaxf(M, fmaxf(fmaxf(sc0, sc1), fmaxf(sc2, sc3)));
        float corr = __expf(M - nM);
        float w0 = __expf(sc0 - nM), w1 = __expf(sc1 - nM);
        float w2 = __expf(sc2 - nM), w3 = __expf(sc3 - nM);
        S = S * corr + ((w0 + w1) + (w2 + w3));
        a0 = a0 * corr + (w0 * x0.x + w1 * x1.x) + (w2 * x2.x + w3 * x3.x);
        a1 = a1 * corr + (w0 * x0.y + w1 * x1.y) + (w2 * x2.y + w3 * x3.y);
        a2 = a2 * corr + (w0 * x0.z + w1 * x1.z) + (w2 * x2.z + w3 * x3.z);
        a3 = a3 * corr + (w0 * x0.w + w1 * x1.w) + (w2 * x2.w + w3 * x3.w);
        M = nM;
    }
    for (; p < end; p++) {
        int2 se = d_cse[p];
        float4 x0;
        float sc;
        EDGE_PRE(se, x0, sc);
        sc += __shfl_xor_sync(0xffffffffu, sc, 1);
        sc += __shfl_xor_sync(0xffffffffu, sc, 2);
        sc += __shfl_xor_sync(0xffffffffu, sc, 4);
        float nM = fmaxf(M, sc);
        float corr = __expf(M - nM);
        float w = __expf(sc - nM);
        S = S * corr + w;
        a0 = a0 * corr + w * x0.x;
        a1 = a1 * corr + w * x0.y;
        a2 = a2 * corr + w * x0.z;
        a3 = a3 * corr + w * x0.w;
        M = nM;
    }
    float inv = 1.0f / (S + 1e-16f);
    float4 cb4 = *(const float4*)&cb[4 * l];
    float hc0 = a0 * inv + cb4.x;
    float hc1 = a1 * inv + cb4.y;
    float hc2 = a2 * inv + cb4.z;
    float hc3 = a3 * inv + cb4.w;

    // fused post: LN + FiLM + GELU + residual
    float mean = wsum(hc0 + hc1 + hc2 + hc3) * (1.0f / 128.0f);
    float v0 = hc0 - mean, v1 = hc1 - mean, v2 = hc2 - mean, v3 = hc3 - mean;
    float var = wsum(v0 * v0 + v1 * v1 + v2 * v2 + v3 * v3) * (1.0f / 128.0f);
    float r = rsqrtf(var + 1e-5f);
    float4 lg4 = *(const float4*)&lng[4 * l];
    float4 lb4 = *(const float4*)&lnb[4 * l];
    float4 gm4 = *(const float4*)&d_gb[layer * 256 + 4 * l];
    float4 bt4 = *(const float4*)&d_gb[layer * 256 + 128 + 4 * l];
    float4 hold = *(const float4*)&d_h[(size_t)t * 128 + 4 * l];
    float h0 = geluf(gm4.x * (v0 * r * lg4.x + lb4.x) + bt4.x) + hold.x;
    float h1 = geluf(gm4.y * (v1 * r * lg4.y + lb4.y) + bt4.y) + hold.y;
    float h2 = geluf(gm4.z * (v2 * r * lg4.z + lb4.z) + bt4.z) + hold.z;
    float h3 = geluf(gm4.w * (v3 * r * lg4.w + lb4.w) + bt4.w) + hold.w;
    *(float4*)&d_h[(size_t)t * 128 + 4 * l] = make_float4(h0, h1, h2, h3);
    if (layer < 3) {
        uint2 hp = make_uint2(pack_hi(h0, h1), pack_hi(h2, h3));
        uint2 lp = make_uint2(pack_lo(h0, h1), pack_lo(h2, h3));
        *(uint2*)(d_hA + (size_t)t * 512 + 8 * l)       = hp;
        *(uint2*)(d_hA + (size_t)t * 512 + 256 + 8 * l) = lp;
    }
}

// ---------------- decoder + masks + nc/delta write ----------------
__global__ void k_dec(const float* x, const unsigned char* fx, const unsigned char* fy,
                      const float* W1, const float* b1, const float* W2, const float* b2,
                      float* out) {
    __shared__ float W1s[128 * 64];
    __shared__ float W2s[128];
    __shared__ float b1s[64];
    __shared__ float b2s[2];
    __shared__ float hs[8][128];
    int tid = threadIdx.x;
    for (int i = tid; i < 128 * 64; i += 256) W1s[i] = W1[i];
    if (tid < 128) W2s[tid] = W2[tid];
    if (tid < 64) b1s[tid] = b1[tid];
    if (tid < 2) b2s[tid] = b2[tid];
    int warp = tid >> 5, lane = tid & 31;
    int t = blockIdx.x * 8 + warp;
    if (t < Nn) {
        #pragma unroll
        for (int k = 0; k < 4; k++) hs[warp][lane + 32 * k] = d_h[t * 128 + lane + 32 * k];
    }
    __syncthreads();
    if (t >= Nn) return;
    int j1 = lane, j2 = lane + 32;
    float t1a = b1s[j1], t1b = b1s[j2];
    #pragma unroll 8
    for (int k = 0; k < 128; k++) {
        float hk = hs[warp][k];
        t1a += hk * W1s[k * 64 + j1];
        t1b += hk * W1s[k * 64 + j2];
    }
    float g1a = geluf(t1a), g1b = geluf(t1b);
    float dc0 = wsum(g1a * W2s[j1 * 2 + 0] + g1b * W2s[j2 * 2 + 0]);
    float dc1 = wsum(g1a * W2s[j1 * 2 + 1] + g1b * W2s[j2 * 2 + 1]);
    if (lane == 0) {
        dc0 += b2s[0]; dc1 += b2s[1];
        dc0 = fminf(fmaxf(dc0, -50.f), 50.f);
        dc1 = fminf(fmaxf(dc1, -50.f), 50.f);
        float dx = fx[t] ? 0.f : dc0;
        float dy = fy[t] ? 0.f : dc1;
        out[t * 2 + 0] = x[t * 8 + 0] + dx;
        out[t * 2 + 1] = x[t * 8 + 1] + dy;
        out[2 * Nn + t * 2 + 0] = dx;
        out[2 * Nn + t * 2 + 1] = dy;
    }
}

// ------------- join pairs fused: tag / mid / scatter in ONE block ---------------
__global__ void __launch_bounds__(1024, 1) k_joinall(const int* jp, float* out) {
    int j = threadIdx.x;
    int u = jp[j * 2 + 0], v = jp[j * 2 + 1];
    d_tag[u] = -1;
    d_tag[v] = -1;
    __syncthreads();
    float mx = (out[u * 2 + 0] + out[v * 2 + 0]) * 0.5f;
    float my = (out[u * 2 + 1] + out[v * 2 + 1]) * 0.5f;
    atomicMax(&d_tag[u], j);
    atomicMax(&d_tag[v], Pp + j);
    __syncthreads();
    if (d_tag[u] == j) {
        out[u * 2 + 0] = mx;
        out[u * 2 + 1] = my;
    }
    if (d_tag[v] == Pp + j) {
        out[v * 2 + 0] = mx;
        out[v * 2 + 1] = my;
    }
}

// ---------------- launch ----------------
extern "C" void kernel_launch(void* const* d_in, const int* in_sizes, int n_in,
                              void* d_out, int out_size) {
    const float* x      = (const float*)d_in[0];
    const int*   ei     = (const int*)  d_in[1];
    const float* ea     = (const float*)d_in[2];
    const float* tmp    = (const float*)d_in[3];
    const unsigned char* fxm = (const unsigned char*)d_in[4];
    const unsigned char* fym = (const unsigned char*)d_in[5];
    const int*   jp     = (const int*)  d_in[6];
    const float* encW   = (const float*)d_in[7];
    const float* encb   = (const float*)d_in[8];
    const float* encg   = (const float*)d_in[9];
    const float* encbe  = (const float*)d_in[10];
    const float* fW1    = (const float*)d_in[11];
    const float* fb1    = (const float*)d_in[12];
    const float* fW2    = (const float*)d_in[13];
    const float* fb2    = (const float*)d_in[14];
    const float* Wl     = (const float*)d_in[15];
    const float* bl     = (const float*)d_in[16];
    const float* Wr     = (const float*)d_in[17];
    const float* br     = (const float*)d_in[18];
    const float* We     = (const float*)d_in[19];
    const float* att    = (const float*)d_in[20];
    const float* cb     = (const float*)d_in[21];
    const float* lng    = (const float*)d_in[22];
    const float* lnb    = (const float*)d_in[23];
    const float* dW1    = (const float*)d_in[24];
    const float* db1    = (const float*)d_in[25];
    const float* dW2    = (const float*)d_in[26];
    const float* db2    = (const float*)d_in[27];
    float* out = (float*)d_out;

    cudaFuncSetAttribute(k_mma, cudaFuncAttributeMaxDynamicSharedMemorySize, 2 * SMSTG);

    k_pre<<<709 + (Nn + 7) / 8, 256>>>(tmp, fW1, fb1, fW2, fb2, Wl, Wr,
                                       x, encW, encb, encg, encbe);
    k_deg<<<(Ee + 255) / 256, 256>>>(ei);
    k_scan1<<<NBS, 1024>>>();
    k_scan23<<<(Nn + 255) / 256, 256>>>();
    k_fill<<<(ENt + 255) / 256, 256>>>(ei);
    k_loopattr<<<(Nn + 255) / 256, 256>>>(ea);
    for (int i = 0; i < 4; i++) {
        k_mma<<<dim3(NT, 2), 256, 2 * SMSTG>>>(i, bl + i * 128, br + i * 128);
        k_gat<<<(Nn + 7) / 8, 256>>>(ea, We + i * 4 * 128, att + i * 128, cb + i * 128,
                                     lng + i * 128, lnb + i * 128, i);
    }
    k_dec<<<(Nn + 7) / 8, 256>>>(x, fxm, fym, dW1, db1, dW2, db2, out);
    k_joinall<<<1, 1024>>>(jp, out);
}